// round 13
// baseline (speedup 1.0000x reference)
#include <cuda_runtime.h>
#include <cstdint>

// Fuzzy LeNet-5, Yager p=1 == Lukasiewicz: conv_out = relu(max(x+w) - 1);
// relu/maxpool fold into one max over (2x2 pool)x(5x5 field).
// Convs in s16 fixed point (scale 16383) with DPX __viaddmax_s16x2 (1 instr =
// 2 max-plus terms). R13: NT=1024 for occupancy; L1 split 2-way along the
// block chain, L2 split 3-way by channel pairs (warp-uniform splits, smem
// partial-combine); Dense split 8-way.

#define NT 1024
#define SCALE 16383.0f
#define ISCALE (1.0f / 16383.0f)
#define IONE 16383

__device__ __forceinline__ unsigned smem_u32(const void* p) {
    return (unsigned)__cvta_generic_to_shared(p);
}
__device__ __forceinline__ void cp8(float* dst, const float* src) {
    asm volatile("cp.async.ca.shared.global [%0], [%1], 8;\n"
                 :: "r"(smem_u32(dst)), "l"(src));
}
__device__ __forceinline__ void cp16(float* dst, const float* src) {
    asm volatile("cp.async.cg.shared.global [%0], [%1], 16;\n"
                 :: "r"(smem_u32(dst)), "l"(src));
}

// Max-plus chains over blocks [BSTART, BSTART+BCNT) of a pooled cell-pair,
// software-pipelined (next block's X/W loaded before current block's DPX).
// Returns packed s16x2 chain maxima: ca (output pw), cb (output pw+1).
template<int CSTRIDE, int PITCH, int WSTRIDE, int BSTART, int BCNT>
__device__ __forceinline__ void mp_range(const uint32_t* __restrict__ x,
                                         const uint32_t* __restrict__ w,
                                         uint32_t& ca, uint32_t& cb)
{
    uint32_t C0 = 0u, C1 = 0u, D0 = 0u, D1 = 0u;
    const uint32_t* xr0 = x + (BSTART / 5) * CSTRIDE + (BSTART % 5) * PITCH;
    const uint32_t* wr0 = w + BSTART * WSTRIDE;
    uint4 Xa = *reinterpret_cast<const uint4*>(xr0);
    uint4 Xb = *reinterpret_cast<const uint4*>(xr0 + 4);
    uint4 Wv = *reinterpret_cast<const uint4*>(wr0);
    uint32_t w4 = wr0[4];
    #pragma unroll
    for (int i = 0; i < BCNT; ++i) {
        const int nb = (i + 1 < BCNT) ? BSTART + i + 1 : BSTART + i;
        const uint32_t* xr = x + (nb / 5) * CSTRIDE + (nb % 5) * PITCH;
        const uint32_t* wr = w + nb * WSTRIDE;
        const uint4 nXa = *reinterpret_cast<const uint4*>(xr);
        const uint4 nXb = *reinterpret_cast<const uint4*>(xr + 4);
        const uint4 nWv = *reinterpret_cast<const uint4*>(wr);
        const uint32_t nw4 = wr[4];
        C0 = __viaddmax_s16x2(Xa.x, Wv.x, C0);
        C1 = __viaddmax_s16x2(Xa.y, Wv.x, C1);
        D0 = __viaddmax_s16x2(Xa.z, Wv.x, D0);
        D1 = __viaddmax_s16x2(Xa.w, Wv.x, D1);
        C0 = __viaddmax_s16x2(Xa.y, Wv.y, C0);
        C1 = __viaddmax_s16x2(Xa.z, Wv.y, C1);
        D0 = __viaddmax_s16x2(Xa.w, Wv.y, D0);
        D1 = __viaddmax_s16x2(Xb.x, Wv.y, D1);
        C0 = __viaddmax_s16x2(Xa.z, Wv.z, C0);
        C1 = __viaddmax_s16x2(Xa.w, Wv.z, C1);
        D0 = __viaddmax_s16x2(Xb.x, Wv.z, D0);
        D1 = __viaddmax_s16x2(Xb.y, Wv.z, D1);
        C0 = __viaddmax_s16x2(Xa.w, Wv.w, C0);
        C1 = __viaddmax_s16x2(Xb.x, Wv.w, C1);
        D0 = __viaddmax_s16x2(Xb.y, Wv.w, D0);
        D1 = __viaddmax_s16x2(Xb.z, Wv.w, D1);
        C0 = __viaddmax_s16x2(Xb.x, w4, C0);
        C1 = __viaddmax_s16x2(Xb.y, w4, C1);
        D0 = __viaddmax_s16x2(Xb.z, w4, D0);
        D1 = __viaddmax_s16x2(Xb.w, w4, D1);
        Xa = nXa; Xb = nXb; Wv = nWv; w4 = nw4;
    }
    ca = __viaddmax_s16x2(C0, 0u, C1);
    cb = __viaddmax_s16x2(D0, 0u, D1);
}

// dynamic smem layout (32-bit words)
#define OFF_W1R  0       // 720 u32: [c*5+kh][o:6][8] padded (w,w)
#define OFF_P1   736     // 2976 u32: [3][31][32] input pair-rows (128B rows)
#define OFF_P2   3712    // 1248 u32: [6][13][16] L1-out pair-rows (padded)
#define OFF_W2P  4960    // 3840 u32: [16][6][5][8]
#define OFF_L2F  8800    // 400 f (16B aligned)
#define OFF_L3   9200    // 120 f
#define OFF_H    9320    // 84 f
#define OFF_WD   9404    // 10080 f (8B aligned)
#define OFF_WF   19484   // 840 f
#define OFF_BF   20324   // 10 f
#define OFF_W3S  20336   // 22400 f: w3 outputs 0..55 (16B aligned)
#define OFF_PART 42736   // 2432 u32: L1 partials (reused as L2 partials)
#define SMEM_WORDS 45168

__global__ __launch_bounds__(NT, 1)
void lenet_fuzzy_kernel(const float* __restrict__ g_in,
                        const float* __restrict__ g_w1,
                        const float* __restrict__ g_w2,
                        const float* __restrict__ g_w3,
                        const float* __restrict__ g_wd,
                        const float* __restrict__ g_wf,
                        const float* __restrict__ g_bf,
                        float* __restrict__ g_out)
{
    extern __shared__ uint32_t sm[];
    uint32_t* s_w1r = sm + OFF_W1R;
    uint32_t* s_p1  = sm + OFF_P1;
    uint32_t* s_p2  = sm + OFF_P2;
    uint32_t* s_w2p = sm + OFF_W2P;
    float*    s_l2f = reinterpret_cast<float*>(sm + OFF_L2F);
    float*    s_l3  = reinterpret_cast<float*>(sm + OFF_L3);
    float*    s_h   = reinterpret_cast<float*>(sm + OFF_H);
    float*    s_wd  = reinterpret_cast<float*>(sm + OFF_WD);
    float*    s_wf  = reinterpret_cast<float*>(sm + OFF_WF);
    float*    s_bf  = reinterpret_cast<float*>(sm + OFF_BF);
    float*    s_w3f = reinterpret_cast<float*>(sm + OFF_W3S);
    uint32_t* s_pp  = sm + OFF_PART;               // L1 partials
    int*      s_pm  = reinterpret_cast<int*>(sm + OFF_PART);  // L2 partials

    const int b    = blockIdx.x;
    const int tid  = threadIdx.x;
    const int warp = tid >> 5;
    const int lane = tid & 31;

    // ---- group 0: w3 outputs 0..55 -> smem (consumed at L3) ----
    for (int i = tid; i < 5600; i += NT) cp16(s_w3f + 4 * i, g_w3 + 4 * i);
    asm volatile("cp.async.commit_group;\n");
    // ---- group 1: head weights (consumed after L3) ----
    for (int i = tid; i < 5040; i += NT) cp8(s_wd + 2 * i, g_wd + 2 * i);
    for (int i = tid; i < 420;  i += NT) cp8(s_wf + 2 * i, g_wf + 2 * i);
    if (tid < 5) cp8(s_bf + 2 * tid, g_bf + 2 * tid);
    asm volatile("cp.async.commit_group;\n");

    // ---- quantize input DIRECTLY from global into pair-rows ----
    if (tid < 372) {                          // 3 ch * 31 rows * 4 groups
        const int c   = tid / 124;
        const int rem = tid - c * 124;
        const int pr  = rem >> 2;             // pair row 0..30
        const int q   = rem & 3;              // col group: cols 8q..8q+7
        const float* gp = g_in + (size_t)b * 3072 + c * 1024 + pr * 32 + 8 * q;
        const float4 a0 = *reinterpret_cast<const float4*>(gp);
        const float4 a1 = *reinterpret_cast<const float4*>(gp + 4);
        const float4 b0 = *reinterpret_cast<const float4*>(gp + 32);
        const float4 b1 = *reinterpret_cast<const float4*>(gp + 36);
        uint32_t* dst = s_p1 + c * 992 + pr * 32 + 8 * q;
        dst[0] = (uint32_t)(__float2int_rn(a0.x * SCALE) | (__float2int_rn(b0.x * SCALE) << 16));
        dst[1] = (uint32_t)(__float2int_rn(a0.y * SCALE) | (__float2int_rn(b0.y * SCALE) << 16));
        dst[2] = (uint32_t)(__float2int_rn(a0.z * SCALE) | (__float2int_rn(b0.z * SCALE) << 16));
        dst[3] = (uint32_t)(__float2int_rn(a0.w * SCALE) | (__float2int_rn(b0.w * SCALE) << 16));
        dst[4] = (uint32_t)(__float2int_rn(a1.x * SCALE) | (__float2int_rn(b1.x * SCALE) << 16));
        dst[5] = (uint32_t)(__float2int_rn(a1.y * SCALE) | (__float2int_rn(b1.y * SCALE) << 16));
        dst[6] = (uint32_t)(__float2int_rn(a1.z * SCALE) | (__float2int_rn(b1.z * SCALE) << 16));
        dst[7] = (uint32_t)(__float2int_rn(a1.w * SCALE) | (__float2int_rn(b1.w * SCALE) << 16));
    }

    // ---- quantize+pack conv weights; zero P2 pad columns ----
    {
        for (int i = tid; i < 450; i += NT) {
            const int o = i / 75, r = i - o * 75;
            const int rk = r / 5, kw = r - rk * 5;
            const int v = __float2int_rn(g_w1[i] * SCALE);
            s_w1r[rk * 48 + o * 8 + kw] = (uint32_t)(v | (v << 16));
        }
        for (int i = tid; i < 2400; i += NT) {
            const int o = i / 150, r = i - o * 150;
            const int rk = r / 5, kw = r - rk * 5;
            const int v = __float2int_rn(g_w2[i] * SCALE);
            s_w2p[o * 240 + rk * 8 + kw] = (uint32_t)(v | (v << 16));
        }
        for (int i = tid; i < 78; i += NT) {
            s_p2[i * 16 + 14] = 0u;
            s_p2[i * 16 + 15] = 0u;
        }
    }
    __syncthreads();

    // ---- Layer 1 partials: 1216 items = (half h, job j<608 padded).
    //      h uniform per warp (608 = 19 warps). h0 = blocks 0..7, h1 = 8..14.
    for (int item = tid; item < 1216; item += NT) {
        const int h  = (item >= 608);
        const int j  = h ? item - 608 : item;
        const int jj = (j < 588) ? j : 587;
        const int ph  = jj / 42;
        const int rem = jj - ph * 42;
        const int o   = rem / 7;
        const int pwp = rem - o * 7;
        const uint32_t* x = s_p1 + (2 * ph) * 32 + 4 * pwp;
        const uint32_t* w = s_w1r + o * 8;
        uint32_t ca, cb;
        if (h == 0) mp_range<992, 32, 48, 0, 8>(x, w, ca, cb);
        else        mp_range<992, 32, 48, 8, 7>(x, w, ca, cb);
        s_pp[2 * item]     = ca;
        s_pp[2 * item + 1] = cb;
    }
    __syncthreads();

    // ---- Layer 1 finalize -> P2 pair-rows ----
    if (tid < 588) {
        const uint32_t ca = __viaddmax_s16x2(s_pp[2 * tid],     0u, s_pp[2 * (tid + 608)]);
        const uint32_t cb = __viaddmax_s16x2(s_pp[2 * tid + 1], 0u, s_pp[2 * (tid + 608) + 1]);
        const int m0 = max((int)(ca & 0xFFFFu), (int)(ca >> 16));
        const int m1 = max((int)(cb & 0xFFFFu), (int)(cb >> 16));
        const int ph  = tid / 42;
        const int rem = tid - ph * 42;
        const int o   = rem / 7;
        const int pwp = rem - o * 7;
        const uint16_t v0 = (uint16_t)max(m0 - IONE, 0);
        const uint16_t v1 = (uint16_t)max(m1 - IONE, 0);
        uint16_t* p2h = reinterpret_cast<uint16_t*>(s_p2);
        const int pw0 = 2 * pwp;
        if (ph <= 12) {
            p2h[2 * (o * 208 + ph * 16 + pw0)]           = v0;
            p2h[2 * (o * 208 + ph * 16 + pw0 + 1)]       = v1;
        }
        if (ph >= 1) {
            p2h[2 * (o * 208 + (ph - 1) * 16 + pw0) + 1]     = v0;
            p2h[2 * (o * 208 + (ph - 1) * 16 + pw0 + 1) + 1] = v1;
        }
    }
    __syncthreads();

    // ---- Layer 2 partials: 768 items = (part p = tid>>8, cell = tid&255).
    //      p uniform per warp. Part p covers channels 2p, 2p+1 (10 blocks). ----
    if (tid < 768) {
        const int p    = tid >> 8;
        const int cell = tid & 255;
        const int cc   = (cell < 240) ? cell : 239;
        const int o    = cc / 15;
        const int rem  = cc - o * 15;
        const int ph   = rem / 3;
        const int cg   = rem - ph * 3;
        const uint32_t* x = s_p2 + p * 416 + (2 * ph) * 16 + 4 * cg;
        const uint32_t* w = s_w2p + o * 240 + p * 80;
        uint32_t ca, cb;
        mp_range<208, 16, 8, 0, 10>(x, w, ca, cb);
        s_pm[2 * tid]     = max((int)(ca & 0xFFFFu), (int)(ca >> 16));
        s_pm[2 * tid + 1] = max((int)(cb & 0xFFFFu), (int)(cb >> 16));
    }
    __syncthreads();

    // ---- Layer 2 finalize -> s_l2f ----
    if (tid < 240) {
        const int o   = tid / 15;
        const int rem = tid - o * 15;
        const int ph  = rem / 3;
        const int cg  = rem - ph * 3;
        const int m0 = max(s_pm[2 * tid], max(s_pm[2 * (tid + 256)], s_pm[2 * (tid + 512)]));
        const int m1 = max(s_pm[2 * tid + 1], max(s_pm[2 * (tid + 256) + 1], s_pm[2 * (tid + 512) + 1]));
        const int base = o * 25 + ph * 5 + 2 * cg;
        s_l2f[base] = (float)max(m0 - IONE, 0) * ISCALE;
        if (cg < 2) s_l2f[base + 1] = (float)max(m1 - IONE, 0) * ISCALE;
    }
    asm volatile("cp.async.wait_group 1;\n");   // w3[0..55] staged
    __syncthreads();

    // ---- Layer 3: (16->120), 4 threads per output; 0..55 smem, rest global ----
    if (tid < 480) {
        const int o = tid >> 2;
        const int q = tid & 3;
        const float4* x4 = reinterpret_cast<const float4*>(s_l2f) + q * 25;
        float m = 0.f;
        if (o < 56) {
            const float4* w4 = reinterpret_cast<const float4*>(s_w3f) + o * 100 + q * 25;
            #pragma unroll
            for (int k = 0; k < 25; ++k) {
                const float4 wv = w4[k];
                const float4 xv = x4[k];
                m = fmaxf(m, xv.x + wv.x);
                m = fmaxf(m, xv.y + wv.y);
                m = fmaxf(m, xv.z + wv.z);
                m = fmaxf(m, xv.w + wv.w);
            }
        } else {
            const float4* w4 = reinterpret_cast<const float4*>(g_w3) + o * 100 + q * 25;
            #pragma unroll
            for (int k = 0; k < 25; ++k) {
                const float4 wv = w4[k];
                const float4 xv = x4[k];
                m = fmaxf(m, xv.x + wv.x);
                m = fmaxf(m, xv.y + wv.y);
                m = fmaxf(m, xv.z + wv.z);
                m = fmaxf(m, xv.w + wv.w);
            }
        }
        m = fmaxf(m, __shfl_xor_sync(0xffffffffu, m, 1));
        m = fmaxf(m, __shfl_xor_sync(0xffffffffu, m, 2));
        if (q == 0) s_l3[o] = fmaxf(0.f, m - 1.f);
    }
    asm volatile("cp.async.wait_group 0;\n");
    __syncthreads();

    // ---- DenseDefuzzy: h = tanh(l3 @ wd), 8 threads per output ----
    {
        const int q  = tid & 7;
        const int j  = tid >> 3;              // 0..127
        const int jj = (j < 84) ? j : 83;
        float acc = 0.f;
        const int k0 = q * 15;
        #pragma unroll
        for (int k = 0; k < 15; ++k)
            acc += s_l3[k0 + k] * s_wd[(k0 + k) * 84 + jj];
        acc += __shfl_xor_sync(0xffffffffu, acc, 1);
        acc += __shfl_xor_sync(0xffffffffu, acc, 2);
        acc += __shfl_xor_sync(0xffffffffu, acc, 4);
        if (q == 0 && j < 84) s_h[j] = tanhf(acc);
    }
    __syncthreads();

    // ---- fc5 + log_softmax in warp 0 ----
    if (warp == 0) {
        const int l = (lane < 10) ? lane : 9;
        float acc = s_bf[l];
        #pragma unroll
        for (int j = 0; j < 84; ++j)
            acc += s_h[j] * s_wf[j * 10 + l];
        float v = (lane < 10) ? acc : -1e30f;
        #pragma unroll
        for (int s = 16; s; s >>= 1)
            v = fmaxf(v, __shfl_xor_sync(0xffffffffu, v, s));
        float e = (lane < 10) ? expf(acc - v) : 0.f;
        #pragma unroll
        for (int s = 16; s; s >>= 1)
            e += __shfl_xor_sync(0xffffffffu, e, s);
        const float ls = v + logf(e);
        if (lane < 10) g_out[(size_t)b * 10 + lane] = acc - ls;
    }
}

extern "C" void kernel_launch(void* const* d_in, const int* in_sizes, int n_in,
                              void* d_out, int out_size)
{
    const float* inp = (const float*)d_in[0];
    const float* w1  = (const float*)d_in[1];
    const float* w2  = (const float*)d_in[2];
    const float* w3  = (const float*)d_in[3];
    const float* wd  = (const float*)d_in[4];
    const float* wf  = (const float*)d_in[5];
    const float* bf  = (const float*)d_in[6];
    float* out = (float*)d_out;

    const int B = in_sizes[0] / (3 * 32 * 32);
    const int smem_bytes = SMEM_WORDS * 4;
    cudaFuncSetAttribute(lenet_fuzzy_kernel,
                         cudaFuncAttributeMaxDynamicSharedMemorySize, smem_bytes);
    lenet_fuzzy_kernel<<<B, NT, smem_bytes>>>(inp, w1, w2, w3, wd, wf, bf, out);
}

// round 15
// speedup vs baseline: 1.1364x; 1.1364x over previous
#include <cuda_runtime.h>
#include <cstdint>

// Fuzzy LeNet-5, Yager p=1 == Lukasiewicz: conv_out = relu(max(x+w) - 1);
// relu/maxpool fold into one max over (2x2 pool)x(5x5 field).
// All three conv layers in s16 fixed point (scale 16383) with DPX
// __viaddmax_s16x2 (1 instr = 2 max-plus terms).
// R15 = R14 with the w3 sizing bug fixed (24000 packed words, not 9600):
//  - prep kernel quantizes/packs w1, w2, w3 ONCE into device-global buffers
//  - L3 runs in DPX s16 on packed w3/l2 (~2.5x fewer instrs than float)

#define NT 640
#define SCALE 16383.0f
#define ISCALE (1.0f / 16383.0f)
#define IONE 16383

__device__ __align__(16) uint32_t d_w1p[720];     // [c*5+kh][o:6][8] (w,w)
__device__ __align__(16) uint32_t d_w2p[3840];    // [o:16][c*5+kh][8] (w,w)
__device__ __align__(16) uint32_t d_w3p[24000];   // [o:120][pair j:200] (w2j,w2j+1)

// ---- prep: pack conv weights into device-global s16x2 buffers ----
__global__ void prep_kernel(const float* __restrict__ g_w1,
                            const float* __restrict__ g_w2,
                            const float* __restrict__ g_w3)
{
    const int t = blockIdx.x * blockDim.x + threadIdx.x;
    const int n = gridDim.x * blockDim.x;
    for (int i = t; i < 450; i += n) {
        const int o = i / 75, r = i - o * 75;
        const int rk = r / 5, kw = r - rk * 5;
        const int v = __float2int_rn(g_w1[i] * SCALE);
        d_w1p[rk * 48 + o * 8 + kw] = (uint32_t)(v | (v << 16));
    }
    for (int i = t; i < 2400; i += n) {
        const int o = i / 150, r = i - o * 150;
        const int rk = r / 5, kw = r - rk * 5;
        const int v = __float2int_rn(g_w2[i] * SCALE);
        d_w2p[o * 240 + rk * 8 + kw] = (uint32_t)(v | (v << 16));
    }
    for (int j = t; j < 24000; j += n) {
        const int v0 = __float2int_rn(g_w3[2 * j]     * SCALE);
        const int v1 = __float2int_rn(g_w3[2 * j + 1] * SCALE);
        d_w3p[j] = (uint32_t)(v0 | (v1 << 16));
    }
}

__device__ __forceinline__ unsigned smem_u32(const void* p) {
    return (unsigned)__cvta_generic_to_shared(p);
}
__device__ __forceinline__ void cp8(void* dst, const void* src) {
    asm volatile("cp.async.ca.shared.global [%0], [%1], 8;\n"
                 :: "r"(smem_u32(dst)), "l"(src));
}
__device__ __forceinline__ void cp16(void* dst, const void* src) {
    asm volatile("cp.async.cg.shared.global [%0], [%1], 16;\n"
                 :: "r"(smem_u32(dst)), "l"(src));
}

// Pooled max-plus pair of cells, software-pipelined (next block's X/W loaded
// before current block's 20 DPX). x: packed pair-rows at (2ph, 4pwp),
// 16B-aligned. w: weight base; block (c,kh) at w + (c*5+kh)*WSTRIDE.
template<int NC, int CSTRIDE, int PITCH, int WSTRIDE>
__device__ __forceinline__ void mp_pair(const uint32_t* __restrict__ x,
                                        const uint32_t* __restrict__ w,
                                        int& m0, int& m1)
{
    uint32_t A0 = 0u, A1 = 0u, B0 = 0u, B1 = 0u;
    uint4 Xa = *reinterpret_cast<const uint4*>(x);
    uint4 Xb = *reinterpret_cast<const uint4*>(x + 4);
    uint4 Wv = *reinterpret_cast<const uint4*>(w);
    uint32_t w4 = w[4];
    #pragma unroll
    for (int blk = 0; blk < NC * 5; ++blk) {
        const int nb  = (blk + 1 < NC * 5) ? blk + 1 : blk;
        const int nc  = nb / 5, nkh = nb - nc * 5;
        const uint32_t* xr = x + nc * CSTRIDE + nkh * PITCH;
        const uint32_t* wr = w + nb * WSTRIDE;
        const uint4 nXa = *reinterpret_cast<const uint4*>(xr);
        const uint4 nXb = *reinterpret_cast<const uint4*>(xr + 4);
        const uint4 nWv = *reinterpret_cast<const uint4*>(wr);
        const uint32_t nw4 = wr[4];
        A0 = __viaddmax_s16x2(Xa.x, Wv.x, A0);
        A1 = __viaddmax_s16x2(Xa.y, Wv.x, A1);
        B0 = __viaddmax_s16x2(Xa.z, Wv.x, B0);
        B1 = __viaddmax_s16x2(Xa.w, Wv.x, B1);
        A0 = __viaddmax_s16x2(Xa.y, Wv.y, A0);
        A1 = __viaddmax_s16x2(Xa.z, Wv.y, A1);
        B0 = __viaddmax_s16x2(Xa.w, Wv.y, B0);
        B1 = __viaddmax_s16x2(Xb.x, Wv.y, B1);
        A0 = __viaddmax_s16x2(Xa.z, Wv.z, A0);
        A1 = __viaddmax_s16x2(Xa.w, Wv.z, A1);
        B0 = __viaddmax_s16x2(Xb.x, Wv.z, B0);
        B1 = __viaddmax_s16x2(Xb.y, Wv.z, B1);
        A0 = __viaddmax_s16x2(Xa.w, Wv.w, A0);
        A1 = __viaddmax_s16x2(Xb.x, Wv.w, A1);
        B0 = __viaddmax_s16x2(Xb.y, Wv.w, B0);
        B1 = __viaddmax_s16x2(Xb.z, Wv.w, B1);
        A0 = __viaddmax_s16x2(Xb.x, w4, A0);
        A1 = __viaddmax_s16x2(Xb.y, w4, A1);
        B0 = __viaddmax_s16x2(Xb.z, w4, B0);
        B1 = __viaddmax_s16x2(Xb.w, w4, B1);
        Xa = nXa; Xb = nXb; Wv = nWv; w4 = nw4;
    }
    const uint32_t ca = __viaddmax_s16x2(A0, 0u, A1);
    const uint32_t cb = __viaddmax_s16x2(B0, 0u, B1);
    m0 = max((int)(ca & 0xFFFFu), (int)(ca >> 16));   // values <= 32766
    m1 = max((int)(cb & 0xFFFFu), (int)(cb >> 16));
}

// dynamic smem layout (32-bit words)
#define OFF_W1R  0       // 720 u32
#define OFF_P1   736     // 2976 u32: [3][31][32] input pair-rows (128B rows)
#define OFF_P2   3712    // 1248 u32: [6][13][16] L1-out pair-rows (padded)
#define OFF_W2P  4960    // 3840 u32
#define OFF_L2P  8800    // 200 u32: packed s16 l2 (flat 400 halfwords)
#define OFF_L3   9000    // 120 f
#define OFF_H    9120    // 84 f
#define OFF_WD   9204    // 10080 f (8B aligned)
#define OFF_WF   19284   // 840 f
#define OFF_BF   20124   // 10 f
#define OFF_W3P  20136   // 24000 u32 packed w3 (16B aligned)
#define SMEM_WORDS 44136

__global__ __launch_bounds__(NT, 1)
void lenet_fuzzy_kernel(const float* __restrict__ g_in,
                        const float* __restrict__ g_wd,
                        const float* __restrict__ g_wf,
                        const float* __restrict__ g_bf,
                        float* __restrict__ g_out)
{
    extern __shared__ uint32_t sm[];
    uint32_t* s_w1r = sm + OFF_W1R;
    uint32_t* s_p1  = sm + OFF_P1;
    uint32_t* s_p2  = sm + OFF_P2;
    uint32_t* s_w2p = sm + OFF_W2P;
    uint32_t* s_l2p = sm + OFF_L2P;
    float*    s_l3  = reinterpret_cast<float*>(sm + OFF_L3);
    float*    s_h   = reinterpret_cast<float*>(sm + OFF_H);
    float*    s_wd  = reinterpret_cast<float*>(sm + OFF_WD);
    float*    s_wf  = reinterpret_cast<float*>(sm + OFF_WF);
    float*    s_bf  = reinterpret_cast<float*>(sm + OFF_BF);
    uint32_t* s_w3p = sm + OFF_W3P;

    const int b    = blockIdx.x;
    const int tid  = threadIdx.x;
    const int warp = tid >> 5;
    const int lane = tid & 31;

    // ---- group A: packed conv weights (needed at L1/L2) ----
    for (int i = tid; i < 180; i += NT) cp16(s_w1r + 4 * i, d_w1p + 4 * i);
    for (int i = tid; i < 960; i += NT) cp16(s_w2p + 4 * i, d_w2p + 4 * i);
    asm volatile("cp.async.commit_group;\n");
    // ---- group B: packed w3, all 120 outputs (needed at L3) ----
    for (int i = tid; i < 6000; i += NT) cp16(s_w3p + 4 * i, d_w3p + 4 * i);
    asm volatile("cp.async.commit_group;\n");
    // ---- group C: head weights (needed after L3) ----
    for (int i = tid; i < 5040; i += NT) cp8(s_wd + 2 * i, g_wd + 2 * i);
    for (int i = tid; i < 420;  i += NT) cp8(s_wf + 2 * i, g_wf + 2 * i);
    if (tid < 5) cp8(s_bf + 2 * tid, g_bf + 2 * tid);
    asm volatile("cp.async.commit_group;\n");

    // ---- quantize input DIRECTLY from global into pair-rows
    //      P1[c][i][col] = (row i, row i+1) ----
    if (tid < 372) {                          // 3 ch * 31 rows * 4 groups
        const int c   = tid / 124;
        const int rem = tid - c * 124;
        const int pr  = rem >> 2;             // pair row 0..30
        const int q   = rem & 3;              // col group: cols 8q..8q+7
        const float* gp = g_in + (size_t)b * 3072 + c * 1024 + pr * 32 + 8 * q;
        const float4 a0 = *reinterpret_cast<const float4*>(gp);
        const float4 a1 = *reinterpret_cast<const float4*>(gp + 4);
        const float4 b0 = *reinterpret_cast<const float4*>(gp + 32);
        const float4 b1 = *reinterpret_cast<const float4*>(gp + 36);
        uint32_t* dst = s_p1 + c * 992 + pr * 32 + 8 * q;
        dst[0] = (uint32_t)(__float2int_rn(a0.x * SCALE) | (__float2int_rn(b0.x * SCALE) << 16));
        dst[1] = (uint32_t)(__float2int_rn(a0.y * SCALE) | (__float2int_rn(b0.y * SCALE) << 16));
        dst[2] = (uint32_t)(__float2int_rn(a0.z * SCALE) | (__float2int_rn(b0.z * SCALE) << 16));
        dst[3] = (uint32_t)(__float2int_rn(a0.w * SCALE) | (__float2int_rn(b0.w * SCALE) << 16));
        dst[4] = (uint32_t)(__float2int_rn(a1.x * SCALE) | (__float2int_rn(b1.x * SCALE) << 16));
        dst[5] = (uint32_t)(__float2int_rn(a1.y * SCALE) | (__float2int_rn(b1.y * SCALE) << 16));
        dst[6] = (uint32_t)(__float2int_rn(a1.z * SCALE) | (__float2int_rn(b1.z * SCALE) << 16));
        dst[7] = (uint32_t)(__float2int_rn(a1.w * SCALE) | (__float2int_rn(b1.w * SCALE) << 16));
    }
    // P2 padding cols 14,15 of each pair-row (read only by discarded chains)
    for (int i = tid; i < 78; i += NT) {
        s_p2[i * 16 + 14] = 0u;
        s_p2[i * 16 + 15] = 0u;
    }
    asm volatile("cp.async.wait_group 2;\n");   // group A (w1/w2) landed
    __syncthreads();

    // ---- Layer 1: (3->6) conv5+relu+pool2, one output-PAIR per thread ----
    if (tid < 588) {                          // 14 rows * 6 ch * 7 pairs
        const int ph  = tid / 42;             // out row 0..13
        const int rem = tid - ph * 42;
        const int o   = rem / 7;              // out channel 0..5
        const int pwp = rem - o * 7;          // pair 0..6 -> cols 2pwp, 2pwp+1
        int m0, m1;
        mp_pair<3, 992, 32, 48>(s_p1 + (2 * ph) * 32 + 4 * pwp, s_w1r + o * 8, m0, m1);
        const uint16_t v0 = (uint16_t)max(m0 - IONE, 0);
        const uint16_t v1 = (uint16_t)max(m1 - IONE, 0);
        uint16_t* p2h = reinterpret_cast<uint16_t*>(s_p2);
        const int pw0 = 2 * pwp;
        // P2[o][i][col]: lo = L1 row i, hi = L1 row i+1  (i in 0..12, stride 16)
        if (ph <= 12) {
            p2h[2 * (o * 208 + ph * 16 + pw0)]           = v0;
            p2h[2 * (o * 208 + ph * 16 + pw0 + 1)]       = v1;
        }
        if (ph >= 1) {
            p2h[2 * (o * 208 + (ph - 1) * 16 + pw0) + 1]     = v0;
            p2h[2 * (o * 208 + (ph - 1) * 16 + pw0 + 1) + 1] = v1;
        }
    }
    __syncthreads();

    // ---- Layer 2: (6->16) conv5+relu+pool2, 2 threads per output-pair
    //      (3 input channels each), shfl-combined; output packed s16 ----
    if (tid < 480) {                          // 16 o * 5 ph * 3 colgroups * 2
        const int half = tid & 1;
        const int pi   = tid >> 1;            // 0..239
        const int o    = pi / 15;
        const int rem  = pi - o * 15;
        const int ph   = rem / 3;             // out row 0..4
        const int cg   = rem - ph * 3;        // colgroup: pw = 2cg, 2cg+1 (cg2: pw 4 only)
        int m0, m1;
        mp_pair<3, 208, 16, 8>(s_p2 + (half * 3) * 208 + (2 * ph) * 16 + 4 * cg,
                               s_w2p + o * 240 + half * 120, m0, m1);
        m0 = max(m0, __shfl_xor_sync(0xffffffffu, m0, 1));
        m1 = max(m1, __shfl_xor_sync(0xffffffffu, m1, 1));
        if (half == 0) {
            uint16_t* l2h = reinterpret_cast<uint16_t*>(s_l2p);
            const int base = o * 25 + ph * 5 + 2 * cg;
            l2h[base] = (uint16_t)max(m0 - IONE, 0);
            if (cg < 2) l2h[base + 1] = (uint16_t)max(m1 - IONE, 0);
        }
    }
    asm volatile("cp.async.wait_group 1;\n");   // packed w3 staged
    __syncthreads();

    // ---- Layer 3: (16->120) in DPX s16, 4 threads per output ----
    if (tid < 480) {
        const int o = tid >> 2;
        const int q = tid & 3;
        const uint2* x2 = reinterpret_cast<const uint2*>(s_l2p) + q * 25;
        const uint2* w2 = reinterpret_cast<const uint2*>(s_w3p + o * 200) + q * 25;
        uint32_t a0 = 0u, a1 = 0u, a2 = 0u, a3 = 0u;
        #pragma unroll
        for (int k = 0; k < 24; k += 2) {
            const uint2 X0 = x2[k],     W0 = w2[k];
            const uint2 X1 = x2[k + 1], W1 = w2[k + 1];
            a0 = __viaddmax_s16x2(X0.x, W0.x, a0);
            a1 = __viaddmax_s16x2(X0.y, W0.y, a1);
            a2 = __viaddmax_s16x2(X1.x, W1.x, a2);
            a3 = __viaddmax_s16x2(X1.y, W1.y, a3);
        }
        {
            const uint2 X0 = x2[24], W0 = w2[24];
            a0 = __viaddmax_s16x2(X0.x, W0.x, a0);
            a1 = __viaddmax_s16x2(X0.y, W0.y, a1);
        }
        const uint32_t c0 = __viaddmax_s16x2(a0, 0u, a1);
        const uint32_t c1 = __viaddmax_s16x2(a2, 0u, a3);
        const uint32_t cc = __viaddmax_s16x2(c0, 0u, c1);
        int m = max((int)(cc & 0xFFFFu), (int)(cc >> 16));
        m = max(m, __shfl_xor_sync(0xffffffffu, m, 1));
        m = max(m, __shfl_xor_sync(0xffffffffu, m, 2));
        if (q == 0) s_l3[o] = (float)max(m - IONE, 0) * ISCALE;
    }
    asm volatile("cp.async.wait_group 0;\n");
    __syncthreads();

    // ---- DenseDefuzzy: h = tanh(l3 @ wd), 4 threads per output ----
    {
        const int q  = tid & 3;
        const int j  = tid >> 2;
        const int jj = (j < 84) ? j : 83;
        float acc = 0.f;
        const int k0 = q * 30;
        #pragma unroll
        for (int k = 0; k < 30; ++k)
            acc += s_l3[k0 + k] * s_wd[(k0 + k) * 84 + jj];
        acc += __shfl_xor_sync(0xffffffffu, acc, 1);
        acc += __shfl_xor_sync(0xffffffffu, acc, 2);
        if (q == 0 && j < 84) s_h[j] = tanhf(acc);
    }
    __syncthreads();

    // ---- fc5 + log_softmax in warp 0 ----
    if (warp == 0) {
        const int l = (lane < 10) ? lane : 9;
        float acc = s_bf[l];
        #pragma unroll
        for (int j = 0; j < 84; ++j)
            acc += s_h[j] * s_wf[j * 10 + l];
        float v = (lane < 10) ? acc : -1e30f;
        #pragma unroll
        for (int s = 16; s; s >>= 1)
            v = fmaxf(v, __shfl_xor_sync(0xffffffffu, v, s));
        float e = (lane < 10) ? expf(acc - v) : 0.f;
        #pragma unroll
        for (int s = 16; s; s >>= 1)
            e += __shfl_xor_sync(0xffffffffu, e, s);
        const float ls = v + logf(e);
        if (lane < 10) g_out[(size_t)b * 10 + lane] = acc - ls;
    }
}

extern "C" void kernel_launch(void* const* d_in, const int* in_sizes, int n_in,
                              void* d_out, int out_size)
{
    const float* inp = (const float*)d_in[0];
    const float* w1  = (const float*)d_in[1];
    const float* w2  = (const float*)d_in[2];
    const float* w3  = (const float*)d_in[3];
    const float* wd  = (const float*)d_in[4];
    const float* wf  = (const float*)d_in[5];
    const float* bf  = (const float*)d_in[6];
    float* out = (float*)d_out;

    const int B = in_sizes[0] / (3 * 32 * 32);
    prep_kernel<<<28, 512>>>(w1, w2, w3);
    const int smem_bytes = SMEM_WORDS * 4;
    cudaFuncSetAttribute(lenet_fuzzy_kernel,
                         cudaFuncAttributeMaxDynamicSharedMemorySize, smem_bytes);
    lenet_fuzzy_kernel<<<B, NT, smem_bytes>>>(inp, wd, wf, bf, out);
}